// round 5
// baseline (speedup 1.0000x reference)
#include <cuda_runtime.h>
#include <cuda_bf16.h>
#include <math.h>
#include <stdint.h>

#define LSEQ   2048
#define DMODEL 1024
#define DINNER 2048
#define DSTATE 16
#define DTRANK 64
#define DCONV  4
#define NDBC   96
#define KSPLIT 8

// ---------------- scratch ----------------
__device__ float g_xz   [LSEQ * 2 * DINNER];
__device__ float g_xc   [LSEQ * DINNER];
__device__ float g_dbc  [LSEQ * NDBC];
__device__ float g_dbcp [KSPLIT * LSEQ * NDBC];
__device__ float g_delta[LSEQ * DINNER];

__device__ __nv_bfloat16 g_xhi [LSEQ * DMODEL],  g_xlo [LSEQ * DMODEL];
__device__ __nv_bfloat16 g_xihi[LSEQ * DINNER],  g_xilo[LSEQ * DINNER];
__device__ __nv_bfloat16 g_yhi [LSEQ * DINNER],  g_ylo [LSEQ * DINNER];
__device__ __nv_bfloat16 g_win_hi [2 * DINNER * DMODEL], g_win_lo [2 * DINNER * DMODEL];
__device__ __nv_bfloat16 g_wcv_hi [DINNER * 4096],       g_wcv_lo [DINNER * 4096];
__device__ __nv_bfloat16 g_wout_hi[DMODEL * DINNER],     g_wout_lo[DMODEL * DINNER];

// ---------------- PTX helpers ----------------
__device__ __forceinline__ uint32_t smem_u32(const void* p) {
    uint32_t a;
    asm("{ .reg .u64 t; cvta.to.shared.u64 t, %1; cvt.u32.u64 %0, t; }" : "=r"(a) : "l"(p));
    return a;
}
__device__ __forceinline__ void cpasync16(uint32_t dst, const void* src, int srcbytes) {
    asm volatile("cp.async.cg.shared.global [%0], [%1], 16, %2;"
                 :: "r"(dst), "l"(src), "r"(srcbytes) : "memory");
}
#define CP_COMMIT()  asm volatile("cp.async.commit_group;" ::: "memory")
#define CP_WAIT(n)   asm volatile("cp.async.wait_group %0;" :: "n"(n) : "memory")

__device__ __forceinline__ void ldsm4(uint32_t& r0, uint32_t& r1, uint32_t& r2, uint32_t& r3,
                                      uint32_t addr) {
    asm volatile("ldmatrix.sync.aligned.m8n8.x4.shared.b16 {%0,%1,%2,%3}, [%4];"
                 : "=r"(r0), "=r"(r1), "=r"(r2), "=r"(r3) : "r"(addr));
}
__device__ __forceinline__ void mma16816(float* c, const uint32_t* a, uint32_t b0, uint32_t b1) {
    asm("mma.sync.aligned.m16n8k16.row.col.f32.bf16.bf16.f32 "
        "{%0,%1,%2,%3},{%4,%5,%6,%7},{%8,%9},{%0,%1,%2,%3};"
        : "+f"(c[0]), "+f"(c[1]), "+f"(c[2]), "+f"(c[3])
        : "r"(a[0]), "r"(a[1]), "r"(a[2]), "r"(a[3]), "r"(b0), "r"(b1));
}

// ---------------- HMMA GEMM: 128x128x32, bf16 hi/lo 3-term, 4-stage ----------------
#define SST       40
#define BUF_ELEMS (128 * SST)
#define STAGE_B   (4 * BUF_ELEMS * 2)
#define NSTAGE    4
#define SMEM_TOT  (NSTAGE * STAGE_B)

// EPI: 0 = store; 1 = +bias silu; 2 = store + bf16 split (cols < DINNER)
template<bool CONV, int EPI>
__global__ __launch_bounds__(256)
void hmma_gemm(const __nv_bfloat16* __restrict__ Ahi, const __nv_bfloat16* __restrict__ Alo, int lda,
               const __nv_bfloat16* __restrict__ Bhi, const __nv_bfloat16* __restrict__ Blo, int ldb,
               float* __restrict__ C, int ldc, int K,
               const float* __restrict__ bias,
               __nv_bfloat16* __restrict__ Shi, __nv_bfloat16* __restrict__ Slo)
{
    extern __shared__ __align__(16) char sm[];
    const uint32_t smb = smem_u32(sm);

    const int tid  = threadIdx.x;
    const int m0   = blockIdx.y * 128;
    const int n0   = blockIdx.x * 128;
    const int grpc = (n0 >> 10) << 10;

    // ---- loader mapping ----
    const int r = tid >> 1;
    const int h = tid & 1;
    const uint32_t sdst = (uint32_t)(r * SST + h * 16) * 2;

    const uint32_t bBase = (uint32_t)(n0 + r) * (uint32_t)ldb + h * 16;
    const uint32_t aBase = CONV ? 0u : (uint32_t)(m0 + r) * (uint32_t)lda + h * 16;
    const int convRow0 = m0 + r - (DCONV - 1);
    const uint32_t convCol = (uint32_t)(grpc + h * 16);

    const int KT = K >> 5;

    auto issue_loads = [&](int kt) {
        const int k0 = kt << 5;
        const uint32_t st = smb + (kt & (NSTAGE - 1)) * STAGE_B;
        uint32_t aoff; int aok = 16;
        if (CONV) {
            int arow = convRow0 + (kt >> 5);
            if (arow < 0) { arow = 0; aok = 0; }
            aoff = (uint32_t)arow * (uint32_t)lda + convCol + (uint32_t)(k0 & 1023);
        } else {
            aoff = aBase + (uint32_t)k0;
        }
        const uint32_t boff = bBase + (uint32_t)k0;
        cpasync16(st + 0 * BUF_ELEMS * 2 + sdst,      Ahi + aoff,     aok);
        cpasync16(st + 0 * BUF_ELEMS * 2 + sdst + 16, Ahi + aoff + 8, aok);
        cpasync16(st + 1 * BUF_ELEMS * 2 + sdst,      Alo + aoff,     aok);
        cpasync16(st + 1 * BUF_ELEMS * 2 + sdst + 16, Alo + aoff + 8, aok);
        cpasync16(st + 2 * BUF_ELEMS * 2 + sdst,      Bhi + boff,     16);
        cpasync16(st + 2 * BUF_ELEMS * 2 + sdst + 16, Bhi + boff + 8, 16);
        cpasync16(st + 3 * BUF_ELEMS * 2 + sdst,      Blo + boff,     16);
        cpasync16(st + 3 * BUF_ELEMS * 2 + sdst + 16, Blo + boff + 8, 16);
        CP_COMMIT();
    };

    // ---- compute mapping ----
    const int wid  = tid >> 5;
    const int lane = tid & 31;
    const int wm   = (wid & 3) * 32;
    const int wn   = (wid >> 2) * 64;
    const int lrow = lane & 15;
    const int lcol = (lane >> 4) << 3;

    float acc[2][8][4];
#pragma unroll
    for (int mt = 0; mt < 2; mt++)
#pragma unroll
        for (int nt = 0; nt < 8; nt++)
#pragma unroll
            for (int q = 0; q < 4; q++) acc[mt][nt][q] = 0.f;

    issue_loads(0);
    issue_loads(1);
    issue_loads(2);

    for (int kt = 0; kt < KT; kt++) {
        CP_WAIT(2);            // stage kt complete
        __syncthreads();       // all threads see stage kt; all done computing kt-1
        if (kt + 3 < KT) issue_loads(kt + 3);   // writes buffer (kt+3)&3 == (kt-1)&3 — safe post-barrier
        else             CP_COMMIT();           // keep group counting aligned

        const uint32_t st = smb + (kt & (NSTAGE - 1)) * STAGE_B;
#pragma unroll
        for (int ks = 0; ks < 2; ks++) {
            const uint32_t coff = (uint32_t)(ks * 16 + lcol) * 2;
            uint32_t afh[2][4], afl[2][4];
#pragma unroll
            for (int mt = 0; mt < 2; mt++) {
                const uint32_t ra = (uint32_t)((wm + mt * 16 + lrow) * SST) * 2 + coff;
                ldsm4(afh[mt][0], afh[mt][1], afh[mt][2], afh[mt][3],
                      st + 0 * BUF_ELEMS * 2 + ra);
                ldsm4(afl[mt][0], afl[mt][1], afl[mt][2], afl[mt][3],
                      st + 1 * BUF_ELEMS * 2 + ra);
            }
#pragma unroll
            for (int p = 0; p < 4; p++) {
                const uint32_t rb = (uint32_t)((wn + p * 16 + lrow) * SST) * 2 + coff;
                uint32_t bh0, bh1, bh2, bh3, bl0, bl1, bl2, bl3;
                ldsm4(bh0, bh1, bh2, bh3, st + 2 * BUF_ELEMS * 2 + rb);
                ldsm4(bl0, bl1, bl2, bl3, st + 3 * BUF_ELEMS * 2 + rb);
                mma16816(acc[0][2 * p],     afh[0], bh0, bh2);
                mma16816(acc[0][2 * p + 1], afh[0], bh1, bh3);
                mma16816(acc[1][2 * p],     afh[1], bh0, bh2);
                mma16816(acc[1][2 * p + 1], afh[1], bh1, bh3);
                mma16816(acc[0][2 * p],     afh[0], bl0, bl2);
                mma16816(acc[0][2 * p + 1], afh[0], bl1, bl3);
                mma16816(acc[1][2 * p],     afh[1], bl0, bl2);
                mma16816(acc[1][2 * p + 1], afh[1], bl1, bl3);
                mma16816(acc[0][2 * p],     afl[0], bh0, bh2);
                mma16816(acc[0][2 * p + 1], afl[0], bh1, bh3);
                mma16816(acc[1][2 * p],     afl[1], bh0, bh2);
                mma16816(acc[1][2 * p + 1], afl[1], bh1, bh3);
            }
        }
    }

    // ---- epilogue ----
    const int qid = lane >> 2;
    const int qt  = lane & 3;
#pragma unroll
    for (int mt = 0; mt < 2; mt++) {
#pragma unroll
        for (int nt = 0; nt < 8; nt++) {
            const int row = m0 + wm + mt * 16 + qid;
            const int col = n0 + wn + nt * 8 + qt * 2;
            float* c = acc[mt][nt];
            if (EPI == 1) {
                const float b0 = bias[col], b1 = bias[col + 1];
                float v;
                v = c[0] + b0; c[0] = v / (1.f + __expf(-v));
                v = c[1] + b1; c[1] = v / (1.f + __expf(-v));
                v = c[2] + b0; c[2] = v / (1.f + __expf(-v));
                v = c[3] + b1; c[3] = v / (1.f + __expf(-v));
            }
            *reinterpret_cast<float2*>(&C[(size_t)row * ldc + col])       = make_float2(c[0], c[1]);
            *reinterpret_cast<float2*>(&C[(size_t)(row + 8) * ldc + col]) = make_float2(c[2], c[3]);
            if (EPI == 2 && col < DINNER) {
#pragma unroll
                for (int rr = 0; rr < 2; rr++) {
                    const int grow = row + rr * 8;
                    const float v0 = c[rr * 2], v1 = c[rr * 2 + 1];
                    const __nv_bfloat16 h0 = __float2bfloat16(v0);
                    const __nv_bfloat16 h1 = __float2bfloat16(v1);
                    __nv_bfloat162 hv, lv;
                    hv.x = h0; hv.y = h1;
                    lv.x = __float2bfloat16(v0 - __bfloat162float(h0));
                    lv.y = __float2bfloat16(v1 - __bfloat162float(h1));
                    *reinterpret_cast<__nv_bfloat162*>(&Shi[(size_t)grow * DINNER + col]) = hv;
                    *reinterpret_cast<__nv_bfloat162*>(&Slo[(size_t)grow * DINNER + col]) = lv;
                }
            }
        }
    }
}

// ---------------- weight transpose + split ----------------
__global__ void wsplit_kernel(const float* __restrict__ W, int K, int N,
                              __nv_bfloat16* __restrict__ Thi, __nv_bfloat16* __restrict__ Tlo)
{
    __shared__ float t[32][33];
    const int k0 = blockIdx.y * 32, n0 = blockIdx.x * 32;
    const int tx = threadIdx.x, ty = threadIdx.y;
#pragma unroll
    for (int j = 0; j < 32; j += 8)
        t[ty + j][tx] = W[(size_t)(k0 + ty + j) * N + n0 + tx];
    __syncthreads();
#pragma unroll
    for (int j = 0; j < 32; j += 8) {
        const float v = t[tx][ty + j];
        const __nv_bfloat16 hv = __float2bfloat16(v);
        const size_t o = (size_t)(n0 + ty + j) * K + k0 + tx;
        Thi[o] = hv;
        Tlo[o] = __float2bfloat16(v - __bfloat162float(hv));
    }
}

__global__ void asplit_kernel(const float* __restrict__ src,
                              __nv_bfloat16* __restrict__ hi, __nv_bfloat16* __restrict__ lo,
                              int total)
{
    const int i = blockIdx.x * blockDim.x + threadIdx.x;
    if (i >= total) return;
    const float v = src[i];
    const __nv_bfloat16 hv = __float2bfloat16(v);
    hi[i] = hv;
    lo[i] = __float2bfloat16(v - __bfloat162float(hv));
}

// ---------------- fp32 SGEMM (small GEMMs) ----------------
template<int EPI, bool SPLITK>
__global__ __launch_bounds__(256, 2)
void sgemm_kernel(const float* __restrict__ A, int lda,
                  const float* __restrict__ B, int ldb,
                  float* __restrict__ C, int ldc,
                  int M, int N, int K, int cstride,
                  const float* __restrict__ bias)
{
    constexpr int BM = 128, BN = 128, BK = 8;
    __shared__ float As[BK][BM];
    __shared__ float Bs[BK][BN];

    if (SPLITK) {
        A += (size_t)blockIdx.z * K;
        B += (size_t)blockIdx.z * K * ldb;
        C += (size_t)blockIdx.z * cstride;
    }

    const int tid = threadIdx.x;
    const int m0  = blockIdx.y * BM;
    const int n0  = blockIdx.x * BN;
    const int tx  = tid & 15;
    const int ty  = tid >> 4;

    const int a_row = tid >> 1;
    const int a_col = (tid & 1) * 4;
    const int b_row = tid >> 5;
    const int b_col = (tid & 31) * 4;

    float acc[8][8];
#pragma unroll
    for (int i = 0; i < 8; i++)
#pragma unroll
        for (int j = 0; j < 8; j++) acc[i][j] = 0.f;

    for (int k0 = 0; k0 < K; k0 += BK) {
        float4 av = *reinterpret_cast<const float4*>(
            &A[(size_t)(m0 + a_row) * lda + (k0 + a_col)]);
        float4 bv = make_float4(0.f, 0.f, 0.f, 0.f);
        if (n0 + b_col + 3 < N)
            bv = *reinterpret_cast<const float4*>(
                &B[(size_t)(k0 + b_row) * ldb + n0 + b_col]);

        __syncthreads();
        As[a_col + 0][a_row] = av.x;
        As[a_col + 1][a_row] = av.y;
        As[a_col + 2][a_row] = av.z;
        As[a_col + 3][a_row] = av.w;
        *reinterpret_cast<float4*>(&Bs[b_row][b_col]) = bv;
        __syncthreads();

#pragma unroll
        for (int kk = 0; kk < BK; kk++) {
            float a[8], b[8];
            *reinterpret_cast<float4*>(&a[0]) = *reinterpret_cast<const float4*>(&As[kk][ty * 4]);
            *reinterpret_cast<float4*>(&a[4]) = *reinterpret_cast<const float4*>(&As[kk][ty * 4 + 64]);
            *reinterpret_cast<float4*>(&b[0]) = *reinterpret_cast<const float4*>(&Bs[kk][tx * 4]);
            *reinterpret_cast<float4*>(&b[4]) = *reinterpret_cast<const float4*>(&Bs[kk][tx * 4 + 64]);
#pragma unroll
            for (int i = 0; i < 8; i++)
#pragma unroll
                for (int j = 0; j < 8; j++)
                    acc[i][j] = fmaf(a[i], b[j], acc[i][j]);
        }
    }

#pragma unroll
    for (int i = 0; i < 8; i++) {
        const int row = m0 + ty * 4 + (i < 4 ? i : 60 + i);
#pragma unroll
        for (int jh = 0; jh < 2; jh++) {
            const int col = n0 + tx * 4 + jh * 64;
            if (col + 3 < N) {
                float out[4];
#pragma unroll
                for (int j = 0; j < 4; j++) {
                    float v = acc[i][jh * 4 + j];
                    if (EPI == 2) {
                        v += bias[col + j];
                        v = (v > 20.f) ? v : log1pf(__expf(v));
                    }
                    out[j] = v;
                }
                *reinterpret_cast<float4*>(&C[(size_t)row * ldc + col]) =
                    make_float4(out[0], out[1], out[2], out[3]);
            }
        }
    }
}

// ---------------- split-K reduce ----------------
__global__ void reduce_k(const float* __restrict__ part, float* __restrict__ dst, int n, int stride)
{
    const int i = blockIdx.x * blockDim.x + threadIdx.x;
    if (i >= n) return;
    float s = 0.f;
#pragma unroll
    for (int z = 0; z < KSPLIT; z++) s += part[(size_t)z * stride + i];
    dst[i] = s;
}

// ---------------- selective scan ----------------
__global__ __launch_bounds__(256)
void scan_kernel(const float* __restrict__ xc,
                 const float* __restrict__ delta,
                 const float* __restrict__ dbc,
                 const float* __restrict__ xz,
                 const float* __restrict__ A_log,
                 const float* __restrict__ Dp,
                 __nv_bfloat16* __restrict__ yhi,
                 __nv_bfloat16* __restrict__ ylo)
{
    const int lane = threadIdx.x & 31;
    const int warp = threadIdx.x >> 5;
    const int chan = (blockIdx.x * 8 + warp) * 2 + (lane >> 4);
    const int n    = lane & 15;

    const float Ad = -__expf(A_log[chan * DSTATE + n]);
    const float Dc = Dp[chan];
    float h = 0.f;

    for (int t = 0; t < LSEQ; t++) {
        const float dt = delta[(size_t)t * DINNER + chan];
        const float u  = xc[(size_t)t * DINNER + chan];
        const float Bt = dbc[(size_t)t * NDBC + DTRANK + n];
        const float Ct = dbc[(size_t)t * NDBC + DTRANK + DSTATE + n];

        const float dA = __expf(dt * Ad);
        h = fmaf(dA, h, dt * u * Bt);

        float yv = h * Ct;
        yv += __shfl_xor_sync(0xffffffffu, yv, 8);
        yv += __shfl_xor_sync(0xffffffffu, yv, 4);
        yv += __shfl_xor_sync(0xffffffffu, yv, 2);
        yv += __shfl_xor_sync(0xffffffffu, yv, 1);

        if (n == 0) {
            const float res = xz[(size_t)t * (2 * DINNER) + DINNER + chan];
            const float sr  = res / (1.f + __expf(-res));
            const float val = (yv + u * Dc) * sr;
            const __nv_bfloat16 hv = __float2bfloat16(val);
            yhi[(size_t)t * DINNER + chan] = hv;
            ylo[(size_t)t * DINNER + chan] = __float2bfloat16(val - __bfloat162float(hv));
        }
    }
}

// ---------------- launch ----------------
extern "C" void kernel_launch(void* const* d_in, const int* in_sizes, int n_in,
                              void* d_out, int out_size)
{
    const float* x         = (const float*)d_in[0];
    const float* in_proj_w = (const float*)d_in[1];
    const float* conv_w    = (const float*)d_in[2];
    const float* conv_b    = (const float*)d_in[3];
    const float* x_proj_w  = (const float*)d_in[4];
    const float* dt_proj_w = (const float*)d_in[5];
    const float* dt_proj_b = (const float*)d_in[6];
    const float* A_log     = (const float*)d_in[7];
    const float* Dp        = (const float*)d_in[8];
    const float* out_proj_w= (const float*)d_in[9];
    float* out = (float*)d_out;

    float *xz, *xc, *dbc, *dbcp, *delta;
    cudaGetSymbolAddress((void**)&xz,    g_xz);
    cudaGetSymbolAddress((void**)&xc,    g_xc);
    cudaGetSymbolAddress((void**)&dbc,   g_dbc);
    cudaGetSymbolAddress((void**)&dbcp,  g_dbcp);
    cudaGetSymbolAddress((void**)&delta, g_delta);

    __nv_bfloat16 *xhi, *xlo, *xihi, *xilo, *yhi, *ylo;
    __nv_bfloat16 *winh, *winl, *wcvh, *wcvl, *wouth, *woutl;
    cudaGetSymbolAddress((void**)&xhi,  g_xhi);   cudaGetSymbolAddress((void**)&xlo,  g_xlo);
    cudaGetSymbolAddress((void**)&xihi, g_xihi);  cudaGetSymbolAddress((void**)&xilo, g_xilo);
    cudaGetSymbolAddress((void**)&yhi,  g_yhi);   cudaGetSymbolAddress((void**)&ylo,  g_ylo);
    cudaGetSymbolAddress((void**)&winh, g_win_hi);  cudaGetSymbolAddress((void**)&winl, g_win_lo);
    cudaGetSymbolAddress((void**)&wcvh, g_wcv_hi);  cudaGetSymbolAddress((void**)&wcvl, g_wcv_lo);
    cudaGetSymbolAddress((void**)&wouth, g_wout_hi); cudaGetSymbolAddress((void**)&woutl, g_wout_lo);

    cudaFuncSetAttribute(hmma_gemm<false, 0>, cudaFuncAttributeMaxDynamicSharedMemorySize, SMEM_TOT);
    cudaFuncSetAttribute(hmma_gemm<false, 2>, cudaFuncAttributeMaxDynamicSharedMemorySize, SMEM_TOT);
    cudaFuncSetAttribute(hmma_gemm<true, 1>,  cudaFuncAttributeMaxDynamicSharedMemorySize, SMEM_TOT);

    dim3 wblk(32, 8);

    wsplit_kernel<<<dim3(4096 / 32, 1024 / 32), wblk>>>(in_proj_w, 1024, 4096, winh, winl);
    wsplit_kernel<<<dim3(2048 / 32, 4096 / 32), wblk>>>(conv_w,    4096, 2048, wcvh, wcvl);
    wsplit_kernel<<<dim3(1024 / 32, 2048 / 32), wblk>>>(out_proj_w,2048, 1024, wouth, woutl);

    asplit_kernel<<<(LSEQ * DMODEL + 255) / 256, 256>>>(x, xhi, xlo, LSEQ * DMODEL);

    // 1) xz = x @ in_proj_w  [2048,4096] K=1024  (+ fused xi split)
    hmma_gemm<false, 2><<<dim3(32, 16), 256, SMEM_TOT>>>(
        xhi, xlo, DMODEL, winh, winl, DMODEL, xz, 2 * DINNER, DMODEL, nullptr, xihi, xilo);

    // 2) xc = silu(conv(xi) + b)  [2048,2048] K=4096
    hmma_gemm<true, 1><<<dim3(16, 16), 256, SMEM_TOT>>>(
        xihi, xilo, DINNER, wcvh, wcvl, 4096, xc, DINNER, 4096, conv_b, nullptr, nullptr);

    // 3) dbc = xc @ x_proj_w  [2048,96] K=2048, split-K x8
    sgemm_kernel<0, true><<<dim3(1, 16, KSPLIT), 256>>>(
        xc, DINNER, x_proj_w, NDBC, dbcp, NDBC, LSEQ, NDBC, DINNER / KSPLIT,
        LSEQ * NDBC, nullptr);
    reduce_k<<<(LSEQ * NDBC + 255) / 256, 256>>>(dbcp, dbc, LSEQ * NDBC, LSEQ * NDBC);

    // 4) delta = softplus(dbc[:, :64] @ dt_proj_w + b)  [2048,2048] K=64
    sgemm_kernel<2, false><<<dim3(16, 16), 256>>>(
        dbc, NDBC, dt_proj_w, DINNER, delta, DINNER, LSEQ, DINNER, DTRANK, 0, dt_proj_b);

    // 5) selective scan (fused y split)
    scan_kernel<<<DINNER / 16, 256>>>(xc, delta, dbc, xz, A_log, Dp, yhi, ylo);

    // 6) out = y @ out_proj_w  [2048,1024] K=2048
    hmma_gemm<false, 0><<<dim3(8, 16), 256, SMEM_TOT>>>(
        yhi, ylo, DINNER, wouth, woutl, DINNER, out, DMODEL, DINNER, nullptr, nullptr, nullptr);
}

// round 6
// speedup vs baseline: 1.0642x; 1.0642x over previous
#include <cuda_runtime.h>
#include <cuda_fp16.h>
#include <math.h>
#include <stdint.h>

#define LSEQ   2048
#define DMODEL 1024
#define DINNER 2048
#define DSTATE 16
#define DTRANK 64
#define DCONV  4
#define NDBC   96
#define KSPLIT 8

// ---------------- scratch ----------------
__device__ float g_xz   [LSEQ * 2 * DINNER];   // only res half written/used
__device__ float g_xc   [LSEQ * DINNER];
__device__ float g_dbc  [LSEQ * NDBC];
__device__ float g_dbcp [KSPLIT * LSEQ * NDBC];
__device__ float g_delta[LSEQ * DINNER];

__device__ __half g_xhi [LSEQ * DMODEL],  g_xlo [LSEQ * DMODEL];
__device__ __half g_xihi[LSEQ * DINNER],  g_xilo[LSEQ * DINNER];
__device__ __half g_yhi [LSEQ * DINNER];                    // 2-term: no lo needed
__device__ __half g_dthi[LSEQ * DTRANK],  g_dtlo[LSEQ * DTRANK];
__device__ __half g_win_hi [2 * DINNER * DMODEL], g_win_lo [2 * DINNER * DMODEL];
__device__ __half g_wcv_hi [DINNER * 4096],       g_wcv_lo [DINNER * 4096];
__device__ __half g_wout_hi[DMODEL * DINNER],     g_wout_lo[DMODEL * DINNER];
__device__ __half g_wdt_hi [DINNER * DTRANK],     g_wdt_lo [DINNER * DTRANK];

// ---------------- PTX helpers ----------------
__device__ __forceinline__ uint32_t smem_u32(const void* p) {
    uint32_t a;
    asm("{ .reg .u64 t; cvta.to.shared.u64 t, %1; cvt.u32.u64 %0, t; }" : "=r"(a) : "l"(p));
    return a;
}
__device__ __forceinline__ void cpasync16(uint32_t dst, const void* src, int srcbytes) {
    asm volatile("cp.async.cg.shared.global [%0], [%1], 16, %2;"
                 :: "r"(dst), "l"(src), "r"(srcbytes) : "memory");
}
#define CP_COMMIT()  asm volatile("cp.async.commit_group;" ::: "memory")
#define CP_WAIT0()   asm volatile("cp.async.wait_group 0;" ::: "memory")

__device__ __forceinline__ void ldsm4(uint32_t& r0, uint32_t& r1, uint32_t& r2, uint32_t& r3,
                                      uint32_t addr) {
    asm volatile("ldmatrix.sync.aligned.m8n8.x4.shared.b16 {%0,%1,%2,%3}, [%4];"
                 : "=r"(r0), "=r"(r1), "=r"(r2), "=r"(r3) : "r"(addr));
}
__device__ __forceinline__ void mma16816(float* c, const uint32_t* a, uint32_t b0, uint32_t b1) {
    asm("mma.sync.aligned.m16n8k16.row.col.f32.f16.f16.f32 "
        "{%0,%1,%2,%3},{%4,%5,%6,%7},{%8,%9},{%0,%1,%2,%3};"
        : "+f"(c[0]), "+f"(c[1]), "+f"(c[2]), "+f"(c[3])
        : "r"(a[0]), "r"(a[1]), "r"(a[2]), "r"(a[3]), "r"(b0), "r"(b1));
}
__device__ __forceinline__ void split2(float v, __half& h, __half& l) {
    h = __float2half_rn(v);
    l = __float2half_rn(v - __half2float(h));
}

// ---------------- HMMA GEMM: 128x128x32, fp16 split, NT terms, 2-stage ----------------
#define SST       40
#define BUF_ELEMS (128 * SST)
#define STAGE_B   (4 * BUF_ELEMS * 2)
#define SMEM_TOT  (2 * STAGE_B)

// EPI: 0 = store fp32; 1 = +bias silu; 2 = in_proj (store res half fp32, split xi to fp16);
//      3 = +bias softplus
// NT:  3 = Ah*Bh + Ah*Bl + Al*Bh ; 2 = Ah*Bh + Ah*Bl (A-lo ignored)
template<bool CONV, int EPI, int NT>
__global__ __launch_bounds__(256, 2)
void hmma_gemm(const __half* __restrict__ Ahi, const __half* __restrict__ Alo, int lda,
               const __half* __restrict__ Bhi, const __half* __restrict__ Blo, int ldb,
               float* __restrict__ C, int ldc, int K,
               const float* __restrict__ bias,
               __half* __restrict__ Shi, __half* __restrict__ Slo)
{
    extern __shared__ __align__(16) char sm[];
    const uint32_t smb = smem_u32(sm);

    const int tid  = threadIdx.x;
    const int m0   = blockIdx.y * 128;
    const int n0   = blockIdx.x * 128;
    const int grpc = (n0 >> 10) << 10;

    // ---- loader mapping: row r = tid>>1, half h = tid&1 (16 fp16 = 32B) ----
    const int r = tid >> 1;
    const int h = tid & 1;
    const uint32_t sdst = (uint32_t)(r * SST + h * 16) * 2;

    const uint32_t bBase = (uint32_t)(n0 + r) * (uint32_t)ldb + h * 16;
    const uint32_t aBase = CONV ? 0u : (uint32_t)(m0 + r) * (uint32_t)lda + h * 16;
    const int convRow0 = m0 + r - (DCONV - 1);
    const uint32_t convCol = (uint32_t)(grpc + h * 16);

    const int KT = K >> 5;

    auto issue_loads = [&](int kt) {
        const int k0 = kt << 5;
        const uint32_t st = smb + (kt & 1) * STAGE_B;
        uint32_t aoff; int aok = 16;
        if (CONV) {
            int arow = convRow0 + (kt >> 5);
            if (arow < 0) { arow = 0; aok = 0; }
            aoff = (uint32_t)arow * (uint32_t)lda + convCol + (uint32_t)(k0 & 1023);
        } else {
            aoff = aBase + (uint32_t)k0;
        }
        const uint32_t boff = bBase + (uint32_t)k0;
        cpasync16(st + 0 * BUF_ELEMS * 2 + sdst,      Ahi + aoff,     aok);
        cpasync16(st + 0 * BUF_ELEMS * 2 + sdst + 16, Ahi + aoff + 8, aok);
        if (NT == 3) {
            cpasync16(st + 1 * BUF_ELEMS * 2 + sdst,      Alo + aoff,     aok);
            cpasync16(st + 1 * BUF_ELEMS * 2 + sdst + 16, Alo + aoff + 8, aok);
        }
        cpasync16(st + 2 * BUF_ELEMS * 2 + sdst,      Bhi + boff,     16);
        cpasync16(st + 2 * BUF_ELEMS * 2 + sdst + 16, Bhi + boff + 8, 16);
        cpasync16(st + 3 * BUF_ELEMS * 2 + sdst,      Blo + boff,     16);
        cpasync16(st + 3 * BUF_ELEMS * 2 + sdst + 16, Blo + boff + 8, 16);
        CP_COMMIT();
    };

    // ---- compute mapping ----
    const int wid  = tid >> 5;
    const int lane = tid & 31;
    const int wm   = (wid & 3) * 32;
    const int wn   = (wid >> 2) * 64;
    const int lrow = lane & 15;
    const int lcol = (lane >> 4) << 3;

    float acc[2][8][4];
#pragma unroll
    for (int mt = 0; mt < 2; mt++)
#pragma unroll
        for (int nt = 0; nt < 8; nt++)
#pragma unroll
            for (int q = 0; q < 4; q++) acc[mt][nt][q] = 0.f;

    issue_loads(0);

    for (int kt = 0; kt < KT; kt++) {
        CP_WAIT0();            // stage kt landed
        __syncthreads();       // visible to all; everyone done computing kt-1
        if (kt + 1 < KT) issue_loads(kt + 1);   // buf (kt+1)&1 last read at kt-1 — safe

        const uint32_t st = smb + (kt & 1) * STAGE_B;
#pragma unroll
        for (int ks = 0; ks < 2; ks++) {
            const uint32_t coff = (uint32_t)(ks * 16 + lcol) * 2;
            uint32_t afh[2][4], afl[2][4];
#pragma unroll
            for (int mt = 0; mt < 2; mt++) {
                const uint32_t ra = (uint32_t)((wm + mt * 16 + lrow) * SST) * 2 + coff;
                ldsm4(afh[mt][0], afh[mt][1], afh[mt][2], afh[mt][3],
                      st + 0 * BUF_ELEMS * 2 + ra);
                if (NT == 3)
                    ldsm4(afl[mt][0], afl[mt][1], afl[mt][2], afl[mt][3],
                          st + 1 * BUF_ELEMS * 2 + ra);
            }
#pragma unroll
            for (int p = 0; p < 4; p++) {
                const uint32_t rb = (uint32_t)((wn + p * 16 + lrow) * SST) * 2 + coff;
                uint32_t bh0, bh1, bh2, bh3, bl0, bl1, bl2, bl3;
                ldsm4(bh0, bh1, bh2, bh3, st + 2 * BUF_ELEMS * 2 + rb);
                ldsm4(bl0, bl1, bl2, bl3, st + 3 * BUF_ELEMS * 2 + rb);
                mma16816(acc[0][2 * p],     afh[0], bh0, bh2);
                mma16816(acc[0][2 * p + 1], afh[0], bh1, bh3);
                mma16816(acc[1][2 * p],     afh[1], bh0, bh2);
                mma16816(acc[1][2 * p + 1], afh[1], bh1, bh3);
                mma16816(acc[0][2 * p],     afh[0], bl0, bl2);
                mma16816(acc[0][2 * p + 1], afh[0], bl1, bl3);
                mma16816(acc[1][2 * p],     afh[1], bl0, bl2);
                mma16816(acc[1][2 * p + 1], afh[1], bl1, bl3);
                if (NT == 3) {
                    mma16816(acc[0][2 * p],     afl[0], bh0, bh2);
                    mma16816(acc[0][2 * p + 1], afl[0], bh1, bh3);
                    mma16816(acc[1][2 * p],     afl[1], bh0, bh2);
                    mma16816(acc[1][2 * p + 1], afl[1], bh1, bh3);
                }
            }
        }
    }

    // ---- epilogue ----
    const int qid = lane >> 2;
    const int qt  = lane & 3;
#pragma unroll
    for (int mt = 0; mt < 2; mt++) {
#pragma unroll
        for (int nt = 0; nt < 8; nt++) {
            const int row = m0 + wm + mt * 16 + qid;
            const int col = n0 + wn + nt * 8 + qt * 2;
            float* c = acc[mt][nt];
            if (EPI == 1 || EPI == 3) {
                const float b0 = bias[col], b1 = bias[col + 1];
                float v;
                if (EPI == 1) {
                    v = c[0] + b0; c[0] = v / (1.f + __expf(-v));
                    v = c[1] + b1; c[1] = v / (1.f + __expf(-v));
                    v = c[2] + b0; c[2] = v / (1.f + __expf(-v));
                    v = c[3] + b1; c[3] = v / (1.f + __expf(-v));
                } else {
                    v = c[0] + b0; c[0] = (v > 20.f) ? v : log1pf(__expf(v));
                    v = c[1] + b1; c[1] = (v > 20.f) ? v : log1pf(__expf(v));
                    v = c[2] + b0; c[2] = (v > 20.f) ? v : log1pf(__expf(v));
                    v = c[3] + b1; c[3] = (v > 20.f) ? v : log1pf(__expf(v));
                }
            }
            if (EPI != 2 || col >= DINNER) {
                *reinterpret_cast<float2*>(&C[(size_t)row * ldc + col])       = make_float2(c[0], c[1]);
                *reinterpret_cast<float2*>(&C[(size_t)(row + 8) * ldc + col]) = make_float2(c[2], c[3]);
            }
            if (EPI == 2 && col < DINNER) {
#pragma unroll
                for (int rr = 0; rr < 2; rr++) {
                    const int grow = row + rr * 8;
                    __half h0, l0, h1, l1;
                    split2(c[rr * 2],     h0, l0);
                    split2(c[rr * 2 + 1], h1, l1);
                    __half2 hv, lv;
                    hv.x = h0; hv.y = h1;
                    lv.x = l0; lv.y = l1;
                    *reinterpret_cast<__half2*>(&Shi[(size_t)grow * DINNER + col]) = hv;
                    *reinterpret_cast<__half2*>(&Slo[(size_t)grow * DINNER + col]) = lv;
                }
            }
        }
    }
}

// ---------------- weight transpose + split ----------------
__global__ void wsplit_kernel(const float* __restrict__ W, int K, int N,
                              __half* __restrict__ Thi, __half* __restrict__ Tlo)
{
    __shared__ float t[32][33];
    const int k0 = blockIdx.y * 32, n0 = blockIdx.x * 32;
    const int tx = threadIdx.x, ty = threadIdx.y;
#pragma unroll
    for (int j = 0; j < 32; j += 8)
        t[ty + j][tx] = W[(size_t)(k0 + ty + j) * N + n0 + tx];
    __syncthreads();
#pragma unroll
    for (int j = 0; j < 32; j += 8) {
        const float v = t[tx][ty + j];
        const size_t o = (size_t)(n0 + ty + j) * K + k0 + tx;
        __half hv, lv;
        split2(v, hv, lv);
        Thi[o] = hv;
        Tlo[o] = lv;
    }
}

__global__ void asplit_kernel(const float* __restrict__ src,
                              __half* __restrict__ hi, __half* __restrict__ lo,
                              int total)
{
    const int i = blockIdx.x * blockDim.x + threadIdx.x;
    if (i >= total) return;
    __half hv, lv;
    split2(src[i], hv, lv);
    hi[i] = hv;
    lo[i] = lv;
}

// ---------------- fp32 SGEMM (x_proj split-K) ----------------
__global__ __launch_bounds__(256, 2)
void sgemm_kernel(const float* __restrict__ A, int lda,
                  const float* __restrict__ B, int ldb,
                  float* __restrict__ C, int ldc,
                  int M, int N, int K, int cstride)
{
    constexpr int BM = 128, BN = 128, BK = 8;
    __shared__ float As[BK][BM];
    __shared__ float Bs[BK][BN];

    A += (size_t)blockIdx.z * K;
    B += (size_t)blockIdx.z * K * ldb;
    C += (size_t)blockIdx.z * cstride;

    const int tid = threadIdx.x;
    const int m0  = blockIdx.y * BM;
    const int n0  = blockIdx.x * BN;
    const int tx  = tid & 15;
    const int ty  = tid >> 4;

    const int a_row = tid >> 1;
    const int a_col = (tid & 1) * 4;
    const int b_row = tid >> 5;
    const int b_col = (tid & 31) * 4;

    float acc[8][8];
#pragma unroll
    for (int i = 0; i < 8; i++)
#pragma unroll
        for (int j = 0; j < 8; j++) acc[i][j] = 0.f;

    for (int k0 = 0; k0 < K; k0 += BK) {
        float4 av = *reinterpret_cast<const float4*>(
            &A[(size_t)(m0 + a_row) * lda + (k0 + a_col)]);
        float4 bv = make_float4(0.f, 0.f, 0.f, 0.f);
        if (n0 + b_col + 3 < N)
            bv = *reinterpret_cast<const float4*>(
                &B[(size_t)(k0 + b_row) * ldb + n0 + b_col]);

        __syncthreads();
        As[a_col + 0][a_row] = av.x;
        As[a_col + 1][a_row] = av.y;
        As[a_col + 2][a_row] = av.z;
        As[a_col + 3][a_row] = av.w;
        *reinterpret_cast<float4*>(&Bs[b_row][b_col]) = bv;
        __syncthreads();

#pragma unroll
        for (int kk = 0; kk < BK; kk++) {
            float a[8], b[8];
            *reinterpret_cast<float4*>(&a[0]) = *reinterpret_cast<const float4*>(&As[kk][ty * 4]);
            *reinterpret_cast<float4*>(&a[4]) = *reinterpret_cast<const float4*>(&As[kk][ty * 4 + 64]);
            *reinterpret_cast<float4*>(&b[0]) = *reinterpret_cast<const float4*>(&Bs[kk][tx * 4]);
            *reinterpret_cast<float4*>(&b[4]) = *reinterpret_cast<const float4*>(&Bs[kk][tx * 4 + 64]);
#pragma unroll
            for (int i = 0; i < 8; i++)
#pragma unroll
                for (int j = 0; j < 8; j++)
                    acc[i][j] = fmaf(a[i], b[j], acc[i][j]);
        }
    }

#pragma unroll
    for (int i = 0; i < 8; i++) {
        const int row = m0 + ty * 4 + (i < 4 ? i : 60 + i);
#pragma unroll
        for (int jh = 0; jh < 2; jh++) {
            const int col = n0 + tx * 4 + jh * 64;
            if (col + 3 < N) {
                *reinterpret_cast<float4*>(&C[(size_t)row * ldc + col]) =
                    make_float4(acc[i][jh * 4], acc[i][jh * 4 + 1],
                                acc[i][jh * 4 + 2], acc[i][jh * 4 + 3]);
            }
        }
    }
}

// ---------------- split-K reduce (+ fused dt fp16 split) ----------------
__global__ void reduce_k(const float* __restrict__ part, float* __restrict__ dst, int n, int stride,
                         __half* __restrict__ dthi, __half* __restrict__ dtlo)
{
    const int i = blockIdx.x * blockDim.x + threadIdx.x;
    if (i >= n) return;
    float s = 0.f;
#pragma unroll
    for (int z = 0; z < KSPLIT; z++) s += part[(size_t)z * stride + i];
    dst[i] = s;
    const int col = i % NDBC;
    if (col < DTRANK) {
        const int row = i / NDBC;
        __half hv, lv;
        split2(s, hv, lv);
        dthi[row * DTRANK + col] = hv;
        dtlo[row * DTRANK + col] = lv;
    }
}

// ---------------- selective scan (writes y fp16 hi only) ----------------
__global__ __launch_bounds__(256)
void scan_kernel(const float* __restrict__ xc,
                 const float* __restrict__ delta,
                 const float* __restrict__ dbc,
                 const float* __restrict__ xz,
                 const float* __restrict__ A_log,
                 const float* __restrict__ Dp,
                 __half* __restrict__ yhi)
{
    const int lane = threadIdx.x & 31;
    const int warp = threadIdx.x >> 5;
    const int chan = (blockIdx.x * 8 + warp) * 2 + (lane >> 4);
    const int n    = lane & 15;

    const float Ad = -__expf(A_log[chan * DSTATE + n]);
    const float Dc = Dp[chan];
    float h = 0.f;

    for (int t = 0; t < LSEQ; t++) {
        const float dt = delta[(size_t)t * DINNER + chan];
        const float u  = xc[(size_t)t * DINNER + chan];
        const float Bt = dbc[(size_t)t * NDBC + DTRANK + n];
        const float Ct = dbc[(size_t)t * NDBC + DTRANK + DSTATE + n];

        const float dA = __expf(dt * Ad);
        h = fmaf(dA, h, dt * u * Bt);

        float yv = h * Ct;
        yv += __shfl_xor_sync(0xffffffffu, yv, 8);
        yv += __shfl_xor_sync(0xffffffffu, yv, 4);
        yv += __shfl_xor_sync(0xffffffffu, yv, 2);
        yv += __shfl_xor_sync(0xffffffffu, yv, 1);

        if (n == 0) {
            const float res = xz[(size_t)t * (2 * DINNER) + DINNER + chan];
            const float sr  = res / (1.f + __expf(-res));
            const float val = (yv + u * Dc) * sr;
            yhi[(size_t)t * DINNER + chan] = __float2half_rn(val);
        }
    }
}

// ---------------- launch ----------------
extern "C" void kernel_launch(void* const* d_in, const int* in_sizes, int n_in,
                              void* d_out, int out_size)
{
    const float* x         = (const float*)d_in[0];
    const float* in_proj_w = (const float*)d_in[1];
    const float* conv_w    = (const float*)d_in[2];
    const float* conv_b    = (const float*)d_in[3];
    const float* x_proj_w  = (const float*)d_in[4];
    const float* dt_proj_w = (const float*)d_in[5];
    const float* dt_proj_b = (const float*)d_in[6];
    const float* A_log     = (const float*)d_in[7];
    const float* Dp        = (const float*)d_in[8];
    const float* out_proj_w= (const float*)d_in[9];
    float* out = (float*)d_out;

    float *xz, *xc, *dbc, *dbcp, *delta;
    cudaGetSymbolAddress((void**)&xz,    g_xz);
    cudaGetSymbolAddress((void**)&xc,    g_xc);
    cudaGetSymbolAddress((void**)&dbc,   g_dbc);
    cudaGetSymbolAddress((void**)&dbcp,  g_dbcp);
    cudaGetSymbolAddress((void**)&delta, g_delta);

    __half *xhi, *xlo, *xihi, *xilo, *yhi, *dthi, *dtlo;
    __half *winh, *winl, *wcvh, *wcvl, *wouth, *woutl, *wdth, *wdtl;
    cudaGetSymbolAddress((void**)&xhi,  g_xhi);   cudaGetSymbolAddress((void**)&xlo,  g_xlo);
    cudaGetSymbolAddress((void**)&xihi, g_xihi);  cudaGetSymbolAddress((void**)&xilo, g_xilo);
    cudaGetSymbolAddress((void**)&yhi,  g_yhi);
    cudaGetSymbolAddress((void**)&dthi, g_dthi);  cudaGetSymbolAddress((void**)&dtlo, g_dtlo);
    cudaGetSymbolAddress((void**)&winh, g_win_hi);  cudaGetSymbolAddress((void**)&winl, g_win_lo);
    cudaGetSymbolAddress((void**)&wcvh, g_wcv_hi);  cudaGetSymbolAddress((void**)&wcvl, g_wcv_lo);
    cudaGetSymbolAddress((void**)&wouth, g_wout_hi); cudaGetSymbolAddress((void**)&woutl, g_wout_lo);
    cudaGetSymbolAddress((void**)&wdth, g_wdt_hi);  cudaGetSymbolAddress((void**)&wdtl, g_wdt_lo);

    cudaFuncSetAttribute(hmma_gemm<false, 2, 3>, cudaFuncAttributeMaxDynamicSharedMemorySize, SMEM_TOT);
    cudaFuncSetAttribute(hmma_gemm<true,  1, 3>, cudaFuncAttributeMaxDynamicSharedMemorySize, SMEM_TOT);
    cudaFuncSetAttribute(hmma_gemm<false, 3, 3>, cudaFuncAttributeMaxDynamicSharedMemorySize, SMEM_TOT);
    cudaFuncSetAttribute(hmma_gemm<false, 0, 2>, cudaFuncAttributeMaxDynamicSharedMemorySize, SMEM_TOT);

    dim3 wblk(32, 8);

    wsplit_kernel<<<dim3(4096 / 32, 1024 / 32), wblk>>>(in_proj_w, 1024, 4096, winh, winl);
    wsplit_kernel<<<dim3(2048 / 32, 4096 / 32), wblk>>>(conv_w,    4096, 2048, wcvh, wcvl);
    wsplit_kernel<<<dim3(1024 / 32, 2048 / 32), wblk>>>(out_proj_w,2048, 1024, wouth, woutl);
    wsplit_kernel<<<dim3(2048 / 32, 64 / 32),   wblk>>>(dt_proj_w,   64, 2048, wdth, wdtl);

    asplit_kernel<<<(LSEQ * DMODEL + 255) / 256, 256>>>(x, xhi, xlo, LSEQ * DMODEL);

    // 1) xz = x @ in_proj_w  [2048,4096] K=1024  (store res half fp32; xi -> fp16 splits)
    hmma_gemm<false, 2, 3><<<dim3(32, 16), 256, SMEM_TOT>>>(
        xhi, xlo, DMODEL, winh, winl, DMODEL, xz, 2 * DINNER, DMODEL, nullptr, xihi, xilo);

    // 2) xc = silu(conv(xi) + b)  [2048,2048] K=4096
    hmma_gemm<true, 1, 3><<<dim3(16, 16), 256, SMEM_TOT>>>(
        xihi, xilo, DINNER, wcvh, wcvl, 4096, xc, DINNER, 4096, conv_b, nullptr, nullptr);

    // 3) dbc = xc @ x_proj_w  [2048,96] K=2048, split-K x8 (+ fused dt split in reduce)
    sgemm_kernel<<<dim3(1, 16, KSPLIT), 256>>>(
        xc, DINNER, x_proj_w, NDBC, dbcp, NDBC, LSEQ, NDBC, DINNER / KSPLIT, LSEQ * NDBC);
    reduce_k<<<(LSEQ * NDBC + 255) / 256, 256>>>(dbcp, dbc, LSEQ * NDBC, LSEQ * NDBC, dthi, dtlo);

    // 4) delta = softplus(dt_r @ dt_proj_w + b)  [2048,2048] K=64  (HMMA 3-term)
    hmma_gemm<false, 3, 3><<<dim3(16, 16), 256, SMEM_TOT>>>(
        dthi, dtlo, DTRANK, wdth, wdtl, DTRANK, delta, DINNER, DTRANK, dt_proj_b, nullptr, nullptr);

    // 5) selective scan (y -> fp16 hi only)
    scan_kernel<<<DINNER / 16, 256>>>(xc, delta, dbc, xz, A_log, Dp, yhi);

    // 6) out = y @ out_proj_w  [2048,1024] K=2048  (2-term: Yh*Wh + Yh*Wl)
    hmma_gemm<false, 0, 2><<<dim3(8, 16), 256, SMEM_TOT>>>(
        yhi, nullptr, DINNER, wouth, woutl, DINNER, out, DMODEL, DINNER, nullptr, nullptr, nullptr);
}